// round 11
// baseline (speedup 1.0000x reference)
#include <cuda_runtime.h>
#include <math.h>

// Dimensions fixed by the problem
#define ED  172          // edge_dim
#define TD  100          // time_dim
#define DQ  356          // embed(256) + time(100)
#define EMB 256          // embed_dim
#define TB  16           // batch rows per block (main kernel)
#define RP  20           // col-major row pitch in main kernel
#define KT  32           // fold-GEMM k-tile depth

// ---- folded-weight scratch (device globals: no allocations allowed) ----
__device__ float g_cv[DQ];                         // bv + cos(t2v_b)@Wv_time
__device__ float g_u[DQ];                          // cv @ Wo + bo
__device__ __align__(16) float g_cpre1[EMB];       // u @ fc1 + fc1_b
__device__ __align__(16) float g_c3[EMB];          // fc2_b @ Wsum + lps_b + lpd_b
__device__ __align__(16) float g_Wsum[EMB * EMB];  // lp_src_w + lp_dst_w
__device__ __align__(16) float g_T[ED * DQ];       // Wv_e @ Wo
__device__ __align__(16) float g_W3[EMB * EMB];    // fc2_w @ Wsum
__device__ __align__(16) float g_M2[ED * EMB];     // T @ fc1

// 8-FMA helper: 2-row (float2 a) x 4-col (float4 w) tile
#define TILE_FMA2(acc, av, wv)                                  \
    do {                                                        \
        float _a0 = (av).x, _a1 = (av).y;                       \
        acc[0][0] = fmaf(_a0, (wv).x, acc[0][0]);               \
        acc[0][1] = fmaf(_a0, (wv).y, acc[0][1]);               \
        acc[0][2] = fmaf(_a0, (wv).z, acc[0][2]);               \
        acc[0][3] = fmaf(_a0, (wv).w, acc[0][3]);               \
        acc[1][0] = fmaf(_a1, (wv).x, acc[1][0]);               \
        acc[1][1] = fmaf(_a1, (wv).y, acc[1][1]);               \
        acc[1][2] = fmaf(_a1, (wv).z, acc[1][2]);               \
        acc[1][3] = fmaf(_a1, (wv).w, acc[1][3]);               \
    } while (0)

// ============================================================
// Tiled fold GEMM: C[M,N] = A[M,K] @ B[K,N]; 32x32 block tile,
// KT=32 k-staging with register prefetch. (unchanged, proven)
// ============================================================
__device__ __forceinline__ void fold_gemm_tile(
    const float* __restrict__ A, int lda, int M,
    const float* __restrict__ B, int ldb, int K, int N,
    float* __restrict__ C, int ldc,
    int tileM, int tileN, float* As /*[KT*36]*/, float* Bs /*[KT*33]*/)
{
    const int tid = threadIdx.x;
    const int m0  = (tid & 7) * 4;
    const int n   = tid >> 3;
    const int nk  = (K + KT - 1) / KT;
    float acc[4] = {0.f, 0.f, 0.f, 0.f};
    float ra[4], rb[4];

    #pragma unroll
    for (int p = 0; p < 4; p++) {
        int idx = tid + 256 * p;
        int gm = tileM + (idx >> 5), gk = idx & 31;
        ra[p] = (gm < M && gk < K) ? A[gm * lda + gk] : 0.f;
        int gk2 = idx >> 5, gn = tileN + (idx & 31);
        rb[p] = (gk2 < K && gn < N) ? B[gk2 * ldb + gn] : 0.f;
    }

    for (int kt = 0; kt < nk; kt++) {
        __syncthreads();
        #pragma unroll
        for (int p = 0; p < 4; p++) {
            int idx = tid + 256 * p;
            As[(idx & 31) * 36 + (idx >> 5)] = ra[p];
            Bs[(idx >> 5) * 33 + (idx & 31)] = rb[p];
        }
        __syncthreads();
        if (kt + 1 < nk) {
            int k0n = (kt + 1) * KT;
            #pragma unroll
            for (int p = 0; p < 4; p++) {
                int idx = tid + 256 * p;
                int gm = tileM + (idx >> 5), gk = k0n + (idx & 31);
                ra[p] = (gm < M && gk < K) ? A[gm * lda + gk] : 0.f;
                int gk2 = k0n + (idx >> 5), gn = tileN + (idx & 31);
                rb[p] = (gk2 < K && gn < N) ? B[gk2 * ldb + gn] : 0.f;
            }
        }
        #pragma unroll
        for (int kk = 0; kk < KT; kk++) {
            float4 a = *(const float4*)(As + kk * 36 + m0);
            float  b = Bs[kk * 33 + n];
            acc[0] = fmaf(a.x, b, acc[0]);
            acc[1] = fmaf(a.y, b, acc[1]);
            acc[2] = fmaf(a.z, b, acc[2]);
            acc[3] = fmaf(a.w, b, acc[3]);
        }
    }
    int gn = tileN + n;
    if (gn < N) {
        #pragma unroll
        for (int i = 0; i < 4; i++) {
            int gm = tileM + m0 + i;
            if (gm < M) C[gm * ldc + gn] = acc[i];
        }
    }
}

// ============================================================
// Parallel GEMV for constant-vector folds (8 k-slices x 32 cols)
// ============================================================
__device__ __forceinline__ void fold_gemv32(
    const float* __restrict__ xs, const float* __restrict__ W, int ldw, int K,
    const float* __restrict__ bias1, const float* __restrict__ bias2,
    float* __restrict__ y, int N, int j0, float* part /*[8*33]*/)
{
    const int tid = threadIdx.x;
    const int jl = tid & 31, slice = tid >> 5;
    const int j = j0 + jl;
    const int chunk = (K + 7) >> 3;
    const int k0 = slice * chunk;
    const int k1 = (k0 + chunk < K) ? (k0 + chunk) : K;
    float s = 0.f;
    if (j < N) {
        #pragma unroll 8
        for (int k = k0; k < k1; k++)
            s = fmaf(xs[k], W[k * ldw + j], s);
    }
    part[slice * 33 + jl] = s;
    __syncthreads();
    if (slice == 0 && j < N) {
        float t = bias1[j];
        if (bias2) t += bias2[j];
        #pragma unroll
        for (int p = 0; p < 8; p++) t += part[p * 33 + jl];
        y[j] = t;
    }
}

// ============================================================
// P1: T = Wv_e @ Wo (72) ; Wsum (16) ; cv GEMV (12)
// ============================================================
#define P1_T   72
#define P1_WS  16
#define P1_CV  12
#define P1_GRID (P1_T + P1_WS + P1_CV)

__global__ void __launch_bounds__(256) tgat_preP1(
    const float* __restrict__ Wv,    const float* __restrict__ bv,
    const float* __restrict__ t2v_b, const float* __restrict__ Wo,
    const float* __restrict__ lps_w, const float* __restrict__ lpd_w)
{
    __shared__ __align__(16) float As[KT * 36];
    __shared__ float Bs[KT * 33];
    __shared__ float xs[TD];
    __shared__ float part[8 * 33];

    const int bid = blockIdx.x;
    const int tid = threadIdx.x;

    if (bid < P1_T) {
        const int NT = 12;
        int tm = (bid / NT) * 32, tn = (bid % NT) * 32;
        fold_gemm_tile(Wv + EMB * DQ, DQ, ED,
                       Wo, DQ, DQ, DQ,
                       g_T, DQ, tm, tn, As, Bs);
    } else if (bid < P1_T + P1_WS) {
        const float4* a4 = (const float4*)lps_w;
        const float4* b4 = (const float4*)lpd_w;
        float4* s4 = (float4*)g_Wsum;
        int nq = (EMB * EMB) / 4;
        for (int i = (bid - P1_T) * 256 + tid; i < nq; i += P1_WS * 256) {
            float4 a = a4[i], b = b4[i];
            s4[i] = make_float4(a.x + b.x, a.y + b.y, a.z + b.z, a.w + b.w);
        }
    } else {
        if (tid < TD) xs[tid] = cosf(t2v_b[tid]);
        __syncthreads();
        int j0 = (bid - P1_T - P1_WS) * 32;
        fold_gemv32(xs, Wv + (EMB + ED) * DQ, DQ, TD, bv, 0, g_cv, DQ, j0, part);
    }
}

// ============================================================
// P2: M2 = T @ fc1 (48) ; W3 = fc2 @ Wsum (64) ; u GEMV (12) ; c3 GEMV (8)
// ============================================================
#define P2_M2  48
#define P2_W3  64
#define P2_U   12
#define P2_C3  8
#define P2_GRID (P2_M2 + P2_W3 + P2_U + P2_C3)

__global__ void __launch_bounds__(256) tgat_preP2(
    const float* __restrict__ fc1_w, const float* __restrict__ fc2_w,
    const float* __restrict__ fc2_b, const float* __restrict__ Wo,
    const float* __restrict__ bo,
    const float* __restrict__ lps_b, const float* __restrict__ lpd_b)
{
    __shared__ __align__(16) float As[KT * 36];
    __shared__ float Bs[KT * 33];
    __shared__ float xs[DQ];
    __shared__ float part[8 * 33];

    const int bid = blockIdx.x;
    const int tid = threadIdx.x;

    if (bid < P2_M2) {
        const int NT = 8;
        int tm = (bid / NT) * 32, tn = (bid % NT) * 32;
        fold_gemm_tile(g_T, DQ, ED,
                       fc1_w, EMB, DQ, EMB,
                       g_M2, EMB, tm, tn, As, Bs);
    } else if (bid < P2_M2 + P2_W3) {
        const int NT = 8;
        int b2 = bid - P2_M2;
        int tm = (b2 / NT) * 32, tn = (b2 % NT) * 32;
        fold_gemm_tile(fc2_w, EMB, EMB,
                       g_Wsum, EMB, EMB, EMB,
                       g_W3, EMB, tm, tn, As, Bs);
    } else if (bid < P2_M2 + P2_W3 + P2_U) {
        for (int k = tid; k < DQ; k += 256) xs[k] = g_cv[k];
        __syncthreads();
        int j0 = (bid - P2_M2 - P2_W3) * 32;
        fold_gemv32(xs, Wo, DQ, DQ, bo, 0, g_u, DQ, j0, part);
    } else {
        for (int k = tid; k < EMB; k += 256) xs[k] = fc2_b[k];
        __syncthreads();
        int j0 = (bid - P2_M2 - P2_W3 - P2_U) * 32;
        fold_gemv32(xs, g_Wsum, EMB, EMB, lps_b, lpd_b, g_c3, EMB, j0, part);
    }
}

// ============================================================
// P3: cpre1 = u @ fc1 + fc1_b  (8 blocks)
// ============================================================
__global__ void __launch_bounds__(256) tgat_preP3(
    const float* __restrict__ fc1_w, const float* __restrict__ fc1_b)
{
    __shared__ float xs[DQ];
    __shared__ float part[8 * 33];
    const int tid = threadIdx.x;
    for (int k = tid; k < DQ; k += 256) xs[k] = g_u[k];
    __syncthreads();
    fold_gemv32(xs, fc1_w, EMB, DQ, fc1_b, 0, g_cpre1, EMB, blockIdx.x * 32, part);
}

// ============================================================
// Main fused kernel: 512 threads (16 warps), TB=16 rows.
// Thread tile = 2 rows x 4 cols (acc 8). Warp pair (2s,2s+1) owns
// 32-col slice s; w&1 selects row half. Weight LDG.128 distance-2
// pipelined (unroll-2 renaming, NO explicit rotation cost);
// activation LDS.64 issued in-body (29-cyc lat, hidden at high occ).
//   stage1: h  = relu(edge @ M2 + cpre1)
//   stage2: hp = relu(h @ W3 + c3)
//   stage3: prob = sigmoid(hp . lpo_w + lpo_b)
// ============================================================
__global__ void __launch_bounds__(512) tgat_main(
    const float* __restrict__ edge,
    const float* __restrict__ lpo_w, const float* __restrict__ lpo_b,
    float* __restrict__ out, int B, int dup)
{
    __shared__ __align__(16) float sbuf[EMB * RP];   // 20.5 KB
    __shared__ float red[8 * TB];                    // 8 col-slices x 16 rows

    const int tid   = threadIdx.x;
    const int lane  = tid & 31;
    const int w     = tid >> 5;
    const int lm8   = lane & 7;
    const int slice = w >> 1;                        // 0..7 (32-col slice)
    const int c0    = slice * 32 + lm8 * 4;
    const int r0    = ((w & 1) * 4 + (lane >> 3)) * 2;   // 0,2,..,14
    const int widx  = c0 >> 2;
    const int b0    = blockIdx.x * TB;
    const int WST   = EMB / 4;                       // float4 stride per weight row

    // transpose-load edge tile: gmem [r][e] -> smem col-major [e][r]
    for (int i = tid; i < TB * ED; i += 512) {
        int r = i / ED, e = i - r * ED;
        sbuf[e * RP + r] = edge[b0 * ED + i];
    }
    __syncthreads();

    float acc[2][4];
    {
        float4 cp = *(const float4*)(g_cpre1 + c0);
        acc[0][0] = cp.x; acc[0][1] = cp.y; acc[0][2] = cp.z; acc[0][3] = cp.w;
        acc[1][0] = cp.x; acc[1][1] = cp.y; acc[1][2] = cp.z; acc[1][3] = cp.w;
    }

    // ---- stage 1: weight-d2 pipeline over e (ED = 172, even) ----
    {
        const float4* Wp = (const float4*)g_M2 + widx;
        const float*  Ap = sbuf + r0;
        float4 w0 = Wp[0], w1 = Wp[WST];
        Wp += 2 * WST;
        #pragma unroll 2
        for (int e = 0; e < ED - 2; e += 2) {
            float4 nw0 = Wp[0], nw1 = Wp[WST];
            Wp += 2 * WST;
            float2 a0 = *(const float2*)(Ap);
            float2 a1 = *(const float2*)(Ap + RP);
            Ap += 2 * RP;
            TILE_FMA2(acc, a0, w0);
            TILE_FMA2(acc, a1, w1);
            w0 = nw0; w1 = nw1;      // absorbed by unroll-2 renaming
        }
        float2 a0 = *(const float2*)(Ap);
        float2 a1 = *(const float2*)(Ap + RP);
        TILE_FMA2(acc, a0, w0);
        TILE_FMA2(acc, a1, w1);
    }

    // pre-issue stage-2 weight prologue (no smem dependence);
    // its L2 latency hides behind the two barriers below
    const float4* Wp2 = (const float4*)g_W3 + widx;
    float4 v0 = Wp2[0], v1 = Wp2[WST];

    __syncthreads();   // edge tile dead

    // h = relu -> col-major h tile (float2 per col, rows r0..r0+1)
    #pragma unroll
    for (int j = 0; j < 4; j++) {
        float2 hv = make_float2(fmaxf(acc[0][j], 0.f), fmaxf(acc[1][j], 0.f));
        *(float2*)(sbuf + (c0 + j) * RP + r0) = hv;
    }
    __syncthreads();

    {
        float4 cc = *(const float4*)(g_c3 + c0);
        acc[0][0] = cc.x; acc[0][1] = cc.y; acc[0][2] = cc.z; acc[0][3] = cc.w;
        acc[1][0] = cc.x; acc[1][1] = cc.y; acc[1][2] = cc.z; acc[1][3] = cc.w;
    }

    // ---- stage 2: same pipeline over k (EMB = 256) ----
    {
        const float*  Ap = sbuf + r0;
        const float4* Wp = Wp2 + 2 * WST;
        #pragma unroll 2
        for (int k = 0; k < EMB - 2; k += 2) {
            float4 nw0 = Wp[0], nw1 = Wp[WST];
            Wp += 2 * WST;
            float2 a0 = *(const float2*)(Ap);
            float2 a1 = *(const float2*)(Ap + RP);
            Ap += 2 * RP;
            TILE_FMA2(acc, a0, v0);
            TILE_FMA2(acc, a1, v1);
            v0 = nw0; v1 = nw1;
        }
        float2 a0 = *(const float2*)(Ap);
        float2 a1 = *(const float2*)(Ap + RP);
        TILE_FMA2(acc, a0, v0);
        TILE_FMA2(acc, a1, v1);
    }

    // ---- stage 3: relu, dot with lpo_w, reduce over lm8 subgroups ----
    {
        float4 wl = *(const float4*)(lpo_w + c0);
        float part[2];
        #pragma unroll
        for (int i = 0; i < 2; i++) {
            part[i] = fmaxf(acc[i][0], 0.f) * wl.x
                    + fmaxf(acc[i][1], 0.f) * wl.y
                    + fmaxf(acc[i][2], 0.f) * wl.z
                    + fmaxf(acc[i][3], 0.f) * wl.w;
        }
        #pragma unroll
        for (int off = 1; off < 8; off <<= 1) {
            part[0] += __shfl_xor_sync(0xffffffffu, part[0], off);
            part[1] += __shfl_xor_sync(0xffffffffu, part[1], off);
        }
        if (lm8 == 0) {
            red[slice * TB + r0]     = part[0];
            red[slice * TB + r0 + 1] = part[1];
        }
    }
    __syncthreads();

    if (tid < TB) {
        float s = lpo_b[0];
        #pragma unroll
        for (int sl = 0; sl < 8; sl++) s += red[sl * TB + tid];
        float prob = 1.f / (1.f + expf(-s));
        int b = b0 + tid;
        if (b < B) {
            out[b] = prob;
            if (dup) out[B + b] = prob;
        }
    }
}

// ============================================================
// Launch. Input order (metadata):
//  0 src 1 dst 2 time 3 edge_feats 4 t2v_w 5 t2v_b
//  6 Wq 7 bq 8 Wk 9 bk 10 Wv 11 bv 12 Wo 13 bo
//  14 fc1_w 15 fc1_b 16 fc2_w 17 fc2_b
//  18 lp_src_w 19 lp_src_b 20 lp_dst_w 21 lp_dst_b 22 lp_out_w 23 lp_out_b
// ============================================================
extern "C" void kernel_launch(void* const* d_in, const int* in_sizes, int n_in,
                              void* d_out, int out_size)
{
    const float* edge  = (const float*)d_in[3];
    const float* t2v_b = (const float*)d_in[5];
    const float* Wv    = (const float*)d_in[10];
    const float* bv    = (const float*)d_in[11];
    const float* Wo    = (const float*)d_in[12];
    const float* bo    = (const float*)d_in[13];
    const float* fc1_w = (const float*)d_in[14];
    const float* fc1_b = (const float*)d_in[15];
    const float* fc2_w = (const float*)d_in[16];
    const float* fc2_b = (const float*)d_in[17];
    const float* lps_w = (const float*)d_in[18];
    const float* lps_b = (const float*)d_in[19];
    const float* lpd_w = (const float*)d_in[20];
    const float* lpd_b = (const float*)d_in[21];
    const float* lpo_w = (const float*)d_in[22];
    const float* lpo_b = (const float*)d_in[23];

    const int B = in_sizes[0];
    float* out = (float*)d_out;
    const int dup = (out_size >= 2 * B) ? 1 : 0;

    tgat_preP1<<<P1_GRID, 256>>>(Wv, bv, t2v_b, Wo, lps_w, lpd_w);
    tgat_preP2<<<P2_GRID, 256>>>(fc1_w, fc2_w, fc2_b, Wo, bo, lps_b, lpd_b);
    tgat_preP3<<<8, 256>>>(fc1_w, fc1_b);
    tgat_main<<<(B + TB - 1) / TB, 512>>>(edge, lpo_w, lpo_b, out, B, dup);
}

// round 12
// speedup vs baseline: 1.8054x; 1.8054x over previous
#include <cuda_runtime.h>
#include <math.h>

// Dimensions fixed by the problem
#define ED  172          // edge_dim
#define TD  100          // time_dim
#define DQ  356          // embed(256) + time(100)
#define EMB 256          // embed_dim
#define TBR 8            // batch rows per block (main kernel)
#define RPX 8            // col-major row pitch in main kernel (8 floats)
#define KT  32           // fold-GEMM k-tile depth

// ---- folded-weight scratch (device globals: no allocations allowed) ----
__device__ float g_cv[DQ];                         // bv + cos(t2v_b)@Wv_time
__device__ float g_u[DQ];                          // cv @ Wo + bo
__device__ __align__(16) float g_cpre1[EMB];       // u @ fc1 + fc1_b
__device__ __align__(16) float g_c3[EMB];          // fc2_b @ Wsum + lps_b + lpd_b
__device__ __align__(16) float g_Wsum[EMB * EMB];  // lp_src_w + lp_dst_w
__device__ __align__(16) float g_T[ED * DQ];       // Wv_e @ Wo
__device__ __align__(16) float g_W3[EMB * EMB];    // fc2_w @ Wsum
__device__ __align__(16) float g_M2[ED * EMB];     // T @ fc1

// 16-FMA helper on a 4x4 accumulator (4 rows from float4 a, 4 cols from float4 w)
#define TILE_FMA(acc, av, wv)                                   \
    do {                                                        \
        float _a0 = (av).x, _a1 = (av).y, _a2 = (av).z, _a3 = (av).w; \
        acc[0][0] = fmaf(_a0, (wv).x, acc[0][0]);               \
        acc[0][1] = fmaf(_a0, (wv).y, acc[0][1]);               \
        acc[0][2] = fmaf(_a0, (wv).z, acc[0][2]);               \
        acc[0][3] = fmaf(_a0, (wv).w, acc[0][3]);               \
        acc[1][0] = fmaf(_a1, (wv).x, acc[1][0]);               \
        acc[1][1] = fmaf(_a1, (wv).y, acc[1][1]);               \
        acc[1][2] = fmaf(_a1, (wv).z, acc[1][2]);               \
        acc[1][3] = fmaf(_a1, (wv).w, acc[1][3]);               \
        acc[2][0] = fmaf(_a2, (wv).x, acc[2][0]);               \
        acc[2][1] = fmaf(_a2, (wv).y, acc[2][1]);               \
        acc[2][2] = fmaf(_a2, (wv).z, acc[2][2]);               \
        acc[2][3] = fmaf(_a2, (wv).w, acc[2][3]);               \
        acc[3][0] = fmaf(_a3, (wv).x, acc[3][0]);               \
        acc[3][1] = fmaf(_a3, (wv).y, acc[3][1]);               \
        acc[3][2] = fmaf(_a3, (wv).z, acc[3][2]);               \
        acc[3][3] = fmaf(_a3, (wv).w, acc[3][3]);               \
    } while (0)

// ============================================================
// Tiled fold GEMM (unchanged, proven)
// ============================================================
__device__ __forceinline__ void fold_gemm_tile(
    const float* __restrict__ A, int lda, int M,
    const float* __restrict__ B, int ldb, int K, int N,
    float* __restrict__ C, int ldc,
    int tileM, int tileN, float* As /*[KT*36]*/, float* Bs /*[KT*33]*/)
{
    const int tid = threadIdx.x;
    const int m0  = (tid & 7) * 4;
    const int n   = tid >> 3;
    const int nk  = (K + KT - 1) / KT;
    float acc[4] = {0.f, 0.f, 0.f, 0.f};
    float ra[4], rb[4];

    #pragma unroll
    for (int p = 0; p < 4; p++) {
        int idx = tid + 256 * p;
        int gm = tileM + (idx >> 5), gk = idx & 31;
        ra[p] = (gm < M && gk < K) ? A[gm * lda + gk] : 0.f;
        int gk2 = idx >> 5, gn = tileN + (idx & 31);
        rb[p] = (gk2 < K && gn < N) ? B[gk2 * ldb + gn] : 0.f;
    }

    for (int kt = 0; kt < nk; kt++) {
        __syncthreads();
        #pragma unroll
        for (int p = 0; p < 4; p++) {
            int idx = tid + 256 * p;
            As[(idx & 31) * 36 + (idx >> 5)] = ra[p];
            Bs[(idx >> 5) * 33 + (idx & 31)] = rb[p];
        }
        __syncthreads();
        if (kt + 1 < nk) {
            int k0n = (kt + 1) * KT;
            #pragma unroll
            for (int p = 0; p < 4; p++) {
                int idx = tid + 256 * p;
                int gm = tileM + (idx >> 5), gk = k0n + (idx & 31);
                ra[p] = (gm < M && gk < K) ? A[gm * lda + gk] : 0.f;
                int gk2 = k0n + (idx >> 5), gn = tileN + (idx & 31);
                rb[p] = (gk2 < K && gn < N) ? B[gk2 * ldb + gn] : 0.f;
            }
        }
        #pragma unroll
        for (int kk = 0; kk < KT; kk++) {
            float4 a = *(const float4*)(As + kk * 36 + m0);
            float  b = Bs[kk * 33 + n];
            acc[0] = fmaf(a.x, b, acc[0]);
            acc[1] = fmaf(a.y, b, acc[1]);
            acc[2] = fmaf(a.z, b, acc[2]);
            acc[3] = fmaf(a.w, b, acc[3]);
        }
    }
    int gn = tileN + n;
    if (gn < N) {
        #pragma unroll
        for (int i = 0; i < 4; i++) {
            int gm = tileM + m0 + i;
            if (gm < M) C[gm * ldc + gn] = acc[i];
        }
    }
}

// ============================================================
// Parallel GEMV for constant-vector folds (8 k-slices x 32 cols)
// ============================================================
__device__ __forceinline__ void fold_gemv32(
    const float* __restrict__ xs, const float* __restrict__ W, int ldw, int K,
    const float* __restrict__ bias1, const float* __restrict__ bias2,
    float* __restrict__ y, int N, int j0, float* part /*[8*33]*/)
{
    const int tid = threadIdx.x;
    const int jl = tid & 31, slice = tid >> 5;
    const int j = j0 + jl;
    const int chunk = (K + 7) >> 3;
    const int k0 = slice * chunk;
    const int k1 = (k0 + chunk < K) ? (k0 + chunk) : K;
    float s = 0.f;
    if (j < N) {
        #pragma unroll 8
        for (int k = k0; k < k1; k++)
            s = fmaf(xs[k], W[k * ldw + j], s);
    }
    part[slice * 33 + jl] = s;
    __syncthreads();
    if (slice == 0 && j < N) {
        float t = bias1[j];
        if (bias2) t += bias2[j];
        #pragma unroll
        for (int p = 0; p < 8; p++) t += part[p * 33 + jl];
        y[j] = t;
    }
}

// ============================================================
// P1: T = Wv_e @ Wo (72) ; Wsum (16) ; cv GEMV (12)
// ============================================================
#define P1_T   72
#define P1_WS  16
#define P1_CV  12
#define P1_GRID (P1_T + P1_WS + P1_CV)

__global__ void __launch_bounds__(256) tgat_preP1(
    const float* __restrict__ Wv,    const float* __restrict__ bv,
    const float* __restrict__ t2v_b, const float* __restrict__ Wo,
    const float* __restrict__ lps_w, const float* __restrict__ lpd_w)
{
    __shared__ __align__(16) float As[KT * 36];
    __shared__ float Bs[KT * 33];
    __shared__ float xs[TD];
    __shared__ float part[8 * 33];

    const int bid = blockIdx.x;
    const int tid = threadIdx.x;

    if (bid < P1_T) {
        const int NT = 12;
        int tm = (bid / NT) * 32, tn = (bid % NT) * 32;
        fold_gemm_tile(Wv + EMB * DQ, DQ, ED,
                       Wo, DQ, DQ, DQ,
                       g_T, DQ, tm, tn, As, Bs);
    } else if (bid < P1_T + P1_WS) {
        const float4* a4 = (const float4*)lps_w;
        const float4* b4 = (const float4*)lpd_w;
        float4* s4 = (float4*)g_Wsum;
        int nq = (EMB * EMB) / 4;
        for (int i = (bid - P1_T) * 256 + tid; i < nq; i += P1_WS * 256) {
            float4 a = a4[i], b = b4[i];
            s4[i] = make_float4(a.x + b.x, a.y + b.y, a.z + b.z, a.w + b.w);
        }
    } else {
        if (tid < TD) xs[tid] = cosf(t2v_b[tid]);
        __syncthreads();
        int j0 = (bid - P1_T - P1_WS) * 32;
        fold_gemv32(xs, Wv + (EMB + ED) * DQ, DQ, TD, bv, 0, g_cv, DQ, j0, part);
    }
}

// ============================================================
// P2: M2 = T @ fc1 (48) ; W3 = fc2 @ Wsum (64) ; u GEMV (12) ; c3 GEMV (8)
// ============================================================
#define P2_M2  48
#define P2_W3  64
#define P2_U   12
#define P2_C3  8
#define P2_GRID (P2_M2 + P2_W3 + P2_U + P2_C3)

__global__ void __launch_bounds__(256) tgat_preP2(
    const float* __restrict__ fc1_w, const float* __restrict__ fc2_w,
    const float* __restrict__ fc2_b, const float* __restrict__ Wo,
    const float* __restrict__ bo,
    const float* __restrict__ lps_b, const float* __restrict__ lpd_b)
{
    __shared__ __align__(16) float As[KT * 36];
    __shared__ float Bs[KT * 33];
    __shared__ float xs[DQ];
    __shared__ float part[8 * 33];

    const int bid = blockIdx.x;
    const int tid = threadIdx.x;

    if (bid < P2_M2) {
        const int NT = 8;
        int tm = (bid / NT) * 32, tn = (bid % NT) * 32;
        fold_gemm_tile(g_T, DQ, ED,
                       fc1_w, EMB, DQ, EMB,
                       g_M2, EMB, tm, tn, As, Bs);
    } else if (bid < P2_M2 + P2_W3) {
        const int NT = 8;
        int b2 = bid - P2_M2;
        int tm = (b2 / NT) * 32, tn = (b2 % NT) * 32;
        fold_gemm_tile(fc2_w, EMB, EMB,
                       g_Wsum, EMB, EMB, EMB,
                       g_W3, EMB, tm, tn, As, Bs);
    } else if (bid < P2_M2 + P2_W3 + P2_U) {
        for (int k = tid; k < DQ; k += 256) xs[k] = g_cv[k];
        __syncthreads();
        int j0 = (bid - P2_M2 - P2_W3) * 32;
        fold_gemv32(xs, Wo, DQ, DQ, bo, 0, g_u, DQ, j0, part);
    } else {
        for (int k = tid; k < EMB; k += 256) xs[k] = fc2_b[k];
        __syncthreads();
        int j0 = (bid - P2_M2 - P2_W3 - P2_U) * 32;
        fold_gemv32(xs, g_Wsum, EMB, EMB, lps_b, lpd_b, g_c3, EMB, j0, part);
    }
}

// ============================================================
// P3: cpre1 = u @ fc1 + fc1_b  (8 blocks)
// ============================================================
__global__ void __launch_bounds__(256) tgat_preP3(
    const float* __restrict__ fc1_w, const float* __restrict__ fc1_b)
{
    __shared__ float xs[DQ];
    __shared__ float part[8 * 33];
    const int tid = threadIdx.x;
    for (int k = tid; k < DQ; k += 256) xs[k] = g_u[k];
    __syncthreads();
    fold_gemv32(xs, fc1_w, EMB, DQ, fc1_b, 0, g_cpre1, EMB, blockIdx.x * 32, part);
}

// ============================================================
// Main fused kernel: R8's proven iteration structure (16 FMA :
// 1 LDG.128 : 1 LDS.128, d2 weight pipeline, unroll-2 renaming)
// at TB=8 rows / 128 threads / 1024 blocks for wave balance
// (6.92 blocks/SM) and high occupancy (~9 blocks/SM resident).
// Warp w (0..3) owns cols [64w, 64w+64); thread tile 4r x 4c:
//   c0 = w*64 + (lane&15)*4,  r0 = (lane>>4)*4.
// ============================================================
__global__ void __launch_bounds__(128) tgat_main(
    const float* __restrict__ edge,
    const float* __restrict__ lpo_w, const float* __restrict__ lpo_b,
    float* __restrict__ out, int B, int dup)
{
    __shared__ __align__(16) float sbuf[EMB * RPX];   // 8 KB: edge tile then h tile
    __shared__ float red[4 * TBR];

    const int tid  = threadIdx.x;
    const int lane = tid & 31;
    const int w    = tid >> 5;                // 0..3
    const int lm16 = lane & 15;
    const int r0   = (lane >> 4) * 4;         // 0 or 4
    const int c0   = w * 64 + lm16 * 4;
    const int widx = c0 >> 2;
    const int b0   = blockIdx.x * TBR;
    const int WST  = EMB / 4;                 // float4 stride per weight row

    // transpose-load edge tile: gmem [r][e] -> smem col-major [e][r]
    for (int i = tid; i < TBR * ED; i += 128) {
        int r = i / ED, e = i - r * ED;
        sbuf[e * RPX + r] = edge[b0 * ED + i];
    }
    __syncthreads();

    float acc[4][4];
    {
        float4 cp = *(const float4*)(g_cpre1 + c0);
        #pragma unroll
        for (int i = 0; i < 4; i++) {
            acc[i][0] = cp.x; acc[i][1] = cp.y; acc[i][2] = cp.z; acc[i][3] = cp.w;
        }
    }

    // ---- stage 1: weight-d2 pipeline over e (ED = 172, even) ----
    {
        const float4* Wp = (const float4*)g_M2 + widx;
        const float*  Ap = sbuf + r0;
        float4 w0 = Wp[0], w1 = Wp[WST];
        Wp += 2 * WST;
        #pragma unroll 2
        for (int e = 0; e < ED - 2; e += 2) {
            float4 nw0 = Wp[0], nw1 = Wp[WST];
            Wp += 2 * WST;
            float4 a0 = *(const float4*)(Ap);
            float4 a1 = *(const float4*)(Ap + RPX);
            Ap += 2 * RPX;
            TILE_FMA(acc, a0, w0);
            TILE_FMA(acc, a1, w1);
            w0 = nw0; w1 = nw1;               // absorbed by unroll-2 renaming
        }
        float4 a0 = *(const float4*)(Ap);
        float4 a1 = *(const float4*)(Ap + RPX);
        TILE_FMA(acc, a0, w0);
        TILE_FMA(acc, a1, w1);
    }

    // pre-issue stage-2 weight prologue (no smem dependence);
    // L2 latency hides behind the two barriers below
    const float4* Wp2 = (const float4*)g_W3 + widx;
    float4 v0 = Wp2[0], v1 = Wp2[WST];

    __syncthreads();   // edge tile dead

    // h = relu -> col-major h tile [k][r], rows r0..r0+3 per col
    #pragma unroll
    for (int j = 0; j < 4; j++) {
        float4 hv = make_float4(fmaxf(acc[0][j], 0.f), fmaxf(acc[1][j], 0.f),
                                fmaxf(acc[2][j], 0.f), fmaxf(acc[3][j], 0.f));
        *(float4*)(sbuf + (c0 + j) * RPX + r0) = hv;
    }
    __syncthreads();

    {
        float4 cc = *(const float4*)(g_c3 + c0);
        #pragma unroll
        for (int i = 0; i < 4; i++) {
            acc[i][0] = cc.x; acc[i][1] = cc.y; acc[i][2] = cc.z; acc[i][3] = cc.w;
        }
    }

    // ---- stage 2: same pipeline over k (EMB = 256) ----
    {
        const float*  Ap = sbuf + r0;
        const float4* Wp = Wp2 + 2 * WST;
        #pragma unroll 2
        for (int k = 0; k < EMB - 2; k += 2) {
            float4 nw0 = Wp[0], nw1 = Wp[WST];
            Wp += 2 * WST;
            float4 a0 = *(const float4*)(Ap);
            float4 a1 = *(const float4*)(Ap + RPX);
            Ap += 2 * RPX;
            TILE_FMA(acc, a0, v0);
            TILE_FMA(acc, a1, v1);
            v0 = nw0; v1 = nw1;
        }
        float4 a0 = *(const float4*)(Ap);
        float4 a1 = *(const float4*)(Ap + RPX);
        TILE_FMA(acc, a0, v0);
        TILE_FMA(acc, a1, v1);
    }

    // ---- stage 3: relu, dot with lpo_w, reduce over the 16 col-positions ----
    {
        float4 wl = *(const float4*)(lpo_w + c0);
        float part[4];
        #pragma unroll
        for (int i = 0; i < 4; i++) {
            part[i] = fmaxf(acc[i][0], 0.f) * wl.x
                    + fmaxf(acc[i][1], 0.f) * wl.y
                    + fmaxf(acc[i][2], 0.f) * wl.z
                    + fmaxf(acc[i][3], 0.f) * wl.w;
        }
        #pragma unroll
        for (int off = 1; off < 16; off <<= 1) {     // reduce within lm16 group
            #pragma unroll
            for (int i = 0; i < 4; i++)
                part[i] += __shfl_xor_sync(0xffffffffu, part[i], off);
        }
        if (lm16 == 0) {
            #pragma unroll
            for (int i = 0; i < 4; i++)
                red[w * TBR + r0 + i] = part[i];     // warp w's 64-col slice sum
        }
    }
    __syncthreads();

    if (tid < TBR) {
        float s = lpo_b[0];
        #pragma unroll
        for (int ww = 0; ww < 4; ww++) s += red[ww * TBR + tid];
        float prob = 1.f / (1.f + expf(-s));
        int b = b0 + tid;
        if (b < B) {
            out[b] = prob;
            if (dup) out[B + b] = prob;
        }
    }
}

// ============================================================
// Launch. Input order (metadata):
//  0 src 1 dst 2 time 3 edge_feats 4 t2v_w 5 t2v_b
//  6 Wq 7 bq 8 Wk 9 bk 10 Wv 11 bv 12 Wo 13 bo
//  14 fc1_w 15 fc1_b 16 fc2_w 17 fc2_b
//  18 lp_src_w 19 lp_src_b 20 lp_dst_w 21 lp_dst_b 22 lp_out_w 23 lp_out_b
// ============================================================
extern "C" void kernel_launch(void* const* d_in, const int* in_sizes, int n_in,
                              void* d_out, int out_size)
{
    const float* edge  = (const float*)d_in[3];
    const float* t2v_b = (const float*)d_in[5];
    const float* Wv    = (const float*)d_in[10];
    const float* bv    = (const float*)d_in[11];
    const float* Wo    = (const float*)d_in[12];
    const float* bo    = (const float*)d_in[13];
    const float* fc1_w = (const float*)d_in[14];
    const float* fc1_b = (const float*)d_in[15];
    const float* fc2_w = (const float*)d_in[16];
    const float* fc2_b = (const float*)d_in[17];
    const float* lps_w = (const float*)d_in[18];
    const float* lps_b = (const float*)d_in[19];
    const float* lpd_w = (const float*)d_in[20];
    const float* lpd_b = (const float*)d_in[21];
    const float* lpo_w = (const float*)d_in[22];
    const float* lpo_b = (const float*)d_in[23];

    const int B = in_sizes[0];
    float* out = (float*)d_out;
    const int dup = (out_size >= 2 * B) ? 1 : 0;

    tgat_preP1<<<P1_GRID, 256>>>(Wv, bv, t2v_b, Wo, lps_w, lpd_w);
    tgat_preP2<<<P2_GRID, 256>>>(fc1_w, fc2_w, fc2_b, Wo, bo, lps_b, lpd_b);
    tgat_preP3<<<8, 256>>>(fc1_w, fc1_b);
    tgat_main<<<(B + TBR - 1) / TBR, 128>>>(edge, lpo_w, lpo_b, out, B, dup);
}